// round 12
// baseline (speedup 1.0000x reference)
#include <cuda_runtime.h>
#include <cuda_fp16.h>
#include <cstdint>

// ================================================================
// AutoGNN, 6 launches:
//   1) split_w:    W1/W2/WL -> fp16 hi/lo (WL padded 40->64 rows)
//   2) gemm_first: Y = fp16(X) @ W1^T   (fp32 X converted in-register)
//   3) gather:     H = fp16(relu(mean(Y[nbrs])))   [packed f32x2 adds]
//   4) gemm_pers:  Y = H @ W2^T        [persistent, W resident, cp.async]
//   5) gather
//   6) gemm_pers<64,40>: out = H @ WL^T (fp32)
// GEMM: mma.sync m16n8k16 fp16, 2-term W split (err 2^-21), fp32 acc.
// ================================================================

#define FEAT 128
#define SAMPLE 25
#define CLASSES 40
#define MAXN 100000
#define RS 272   // smem row stride bytes: conflict-free ldmatrix
#define NCTAS 152

__device__ __half g_Y[(size_t)MAXN * FEAT];
__device__ __half g_H[(size_t)MAXN * FEAT];
__device__ __half g_W1hi[128 * 128], g_W1lo[128 * 128];
__device__ __half g_W2hi[128 * 128], g_W2lo[128 * 128];
__device__ __half g_WLhi[64 * 128],  g_WLlo[64 * 128];

__device__ __forceinline__ uint32_t smem_u32(const void* p) {
    uint32_t a;
    asm("{ .reg .u64 t; cvta.to.shared.u64 t, %1; cvt.u32.u64 %0, t; }" : "=r"(a) : "l"(p));
    return a;
}
__device__ __forceinline__ void ldsm4(uint32_t addr, uint32_t& r0, uint32_t& r1,
                                      uint32_t& r2, uint32_t& r3) {
    asm volatile("ldmatrix.sync.aligned.m8n8.x4.shared.b16 {%0,%1,%2,%3}, [%4];"
                 : "=r"(r0), "=r"(r1), "=r"(r2), "=r"(r3) : "r"(addr));
}
__device__ __forceinline__ void mma_f16(float* c, const uint32_t* a,
                                        uint32_t b0, uint32_t b1) {
    asm volatile(
        "mma.sync.aligned.m16n8k16.row.col.f32.f16.f16.f32 "
        "{%0,%1,%2,%3}, {%4,%5,%6,%7}, {%8,%9}, {%0,%1,%2,%3};"
        : "+f"(c[0]), "+f"(c[1]), "+f"(c[2]), "+f"(c[3])
        : "r"(a[0]), "r"(a[1]), "r"(a[2]), "r"(a[3]), "r"(b0), "r"(b1));
}
__device__ __forceinline__ void cp_async16(uint32_t saddr, const void* gaddr,
                                           uint32_t src_sz) {
    asm volatile("cp.async.cg.shared.global [%0], [%1], 16, %2;"
                 :: "r"(saddr), "l"(gaddr), "r"(src_sz));
}
#define CP_COMMIT() asm volatile("cp.async.commit_group;" ::: "memory")
#define CP_WAIT1()  asm volatile("cp.async.wait_group 1;" ::: "memory")

// ---------------- shared epilogue helper -------------------------------------
template<int WN, int NT, int CST, typename TOUT>
__device__ __forceinline__ void epilogue_store(
    float c[2][NT][4], TOUT* __restrict__ C, int m0, int n,
    int wm, int wn, int lane)
{
    const int qrow = lane >> 2;
    const int qcol = (lane & 3) * 2;
    #pragma unroll
    for (int mt = 0; mt < 2; mt++) {
        #pragma unroll
        for (int half = 0; half < 2; half++) {
            int m_g = m0 + wm * 32 + mt * 16 + qrow + half * 8;
            if (m_g < n) {
                TOUT* crow = C + (size_t)m_g * CST;
                #pragma unroll
                for (int j = 0; j < NT; j++) {
                    int n_g = wn * WN + j * 8 + qcol;
                    if (CST == 128 || n_g < CST) {
                        float v0 = c[mt][j][half * 2];
                        float v1 = c[mt][j][half * 2 + 1];
                        if constexpr (sizeof(TOUT) == 2) {
                            __half2 hv = __floats2half2_rn(v0, v1);
                            *reinterpret_cast<__half2*>(crow + n_g) = hv;
                        } else {
                            *reinterpret_cast<float2*>(crow + n_g) =
                                make_float2(v0, v1);
                        }
                    }
                }
            }
        }
    }
}

// ================================================================
// kernel 2: Y(fp16) = fp16(X) @ W1^T — non-persistent, 8 warps,
// CTA tile 128x128, 2 CTAs/SM. smem: [A 128*RS][Wh 128*RS][Wl 128*RS]
// ================================================================
__global__ __launch_bounds__(256, 2) void gemm_first_kernel(
    const float* __restrict__ X,
    const __half* __restrict__ Wh, const __half* __restrict__ Wl,
    __half* __restrict__ C, int n)
{
    extern __shared__ char smem[];
    constexpr int OFF_WH = 128 * RS;
    constexpr int OFF_WL = OFF_WH + 128 * RS;
    const int tid  = threadIdx.x;
    const int wid  = tid >> 5;
    const int lane = tid & 31;
    const int wm   = wid >> 1;
    const int wn   = wid & 1;
    const int m0   = blockIdx.x * 128;

    #pragma unroll
    for (int i = 0; i < 16; i++) {
        int t = i * 256 + tid;              // 4096 float4
        int row = t >> 5;
        int c4  = t & 31;
        int grow = m0 + row;
        float4 v = make_float4(0.f, 0.f, 0.f, 0.f);
        if (grow < n)
            v = __ldg(reinterpret_cast<const float4*>(X + (size_t)grow * 128) + c4);
        __half h[4] = { __float2half(v.x), __float2half(v.y),
                        __float2half(v.z), __float2half(v.w) };
        *reinterpret_cast<uint2*>(smem + row * RS + c4 * 8) =
            *reinterpret_cast<uint2*>(h);
    }
    #pragma unroll
    for (int i = 0; i < 8; i++) {
        int t = i * 256 + tid;
        int row = t >> 4;
        int c16 = t & 15;
        size_t g = (size_t)row * 128 + c16 * 8;
        int off = row * RS + c16 * 16;
        *reinterpret_cast<uint4*>(smem + OFF_WH + off) =
            *reinterpret_cast<const uint4*>(Wh + g);
        *reinterpret_cast<uint4*>(smem + OFF_WL + off) =
            *reinterpret_cast<const uint4*>(Wl + g);
    }
    __syncthreads();

    const uint32_t sb = smem_u32(smem);
    const int l15   = lane & 15;
    const int aHalf = (lane & 16) ? 16 : 0;
    const uint32_t aRow0 = (uint32_t)((wm * 32 + l15) * RS + aHalf);
    const uint32_t aRow1 = aRow0 + 16 * RS;
    const int bRow  = (lane & 7) + ((lane & 16) ? 8 : 0);
    const int bHalf = (lane & 8) ? 16 : 0;
    uint32_t bRowByte[4];
    #pragma unroll
    for (int jp = 0; jp < 4; jp++)
        bRowByte[jp] = (uint32_t)((wn * 64 + jp * 16 + bRow) * RS + bHalf);

    float c[2][8][4];
    #pragma unroll
    for (int mt = 0; mt < 2; mt++)
        #pragma unroll
        for (int j = 0; j < 8; j++)
            #pragma unroll
            for (int q = 0; q < 4; q++) c[mt][j][q] = 0.f;

    #pragma unroll
    for (int ks = 0; ks < 8; ks++) {
        const uint32_t kb = ks * 32;
        uint32_t a[2][4];
        ldsm4(sb + aRow0 + kb, a[0][0], a[0][1], a[0][2], a[0][3]);
        ldsm4(sb + aRow1 + kb, a[1][0], a[1][1], a[1][2], a[1][3]);
        uint32_t bh[8][2], bl[8][2];
        #pragma unroll
        for (int jp = 0; jp < 4; jp++) {
            ldsm4(sb + OFF_WH + bRowByte[jp] + kb,
                  bh[2 * jp][0], bh[2 * jp][1], bh[2 * jp + 1][0], bh[2 * jp + 1][1]);
            ldsm4(sb + OFF_WL + bRowByte[jp] + kb,
                  bl[2 * jp][0], bl[2 * jp][1], bl[2 * jp + 1][0], bl[2 * jp + 1][1]);
        }
        #pragma unroll
        for (int mt = 0; mt < 2; mt++)
            #pragma unroll
            for (int j = 0; j < 8; j++) {
                mma_f16(c[mt][j], a[mt], bh[j][0], bh[j][1]);
                mma_f16(c[mt][j], a[mt], bl[j][0], bl[j][1]);
            }
    }
    epilogue_store<64, 8, 128>(c, C, m0, n, wm, wn, lane);
}

// ================================================================
// kernels 4/6: persistent GEMM, W resident, A cp.async double-buffered.
// CTA tile 256 x NOUT, 512 threads / 16 warps.
// smem: [Wh NOUT*RS][Wl NOUT*RS][Abuf0 256*RS][Abuf1 256*RS]
// ================================================================
template<int NOUT, int CST, typename TOUT>
__global__ __launch_bounds__(512, 1) void gemm_pers_kernel(
    const __half* __restrict__ A,
    const __half* __restrict__ Wh, const __half* __restrict__ Wl,
    TOUT* __restrict__ C, int n)
{
    extern __shared__ char smem[];
    constexpr int OFF_WL = NOUT * RS;
    constexpr int OFF_A0 = 2 * NOUT * RS;
    constexpr int ABUF   = 256 * RS;
    constexpr int WN = NOUT / 2;
    constexpr int NT = WN / 8;

    const int tid  = threadIdx.x;
    const int wid  = tid >> 5;
    const int lane = tid & 31;
    const int wm   = wid >> 1;         // 0..7
    const int wn   = wid & 1;          // 0..1
    const uint32_t sb = smem_u32(smem);

    #pragma unroll
    for (int i = 0; i < NOUT / 32; i++) {
        int t = i * 512 + tid;
        int row = t >> 4;
        int c16 = t & 15;
        size_t g = (size_t)row * 128 + c16 * 8;
        int off = row * RS + c16 * 16;
        *reinterpret_cast<uint4*>(smem + off) =
            *reinterpret_cast<const uint4*>(Wh + g);
        *reinterpret_cast<uint4*>(smem + OFF_WL + off) =
            *reinterpret_cast<const uint4*>(Wl + g);
    }

    const int tiles  = (n + 255) >> 8;
    const int stride = gridDim.x;

    auto prefetch = [&](int t, int buf) {
        const uint32_t abase = sb + OFF_A0 + buf * ABUF;
        const int m0 = t << 8;
        #pragma unroll
        for (int i = 0; i < 8; i++) {
            int k = i * 512 + tid;
            int row = k >> 4;
            int c16 = k & 15;
            int grow = m0 + row;
            uint32_t sz = (grow < n) ? 16u : 0u;
            int gc = (grow < n) ? grow : 0;
            size_t g = (size_t)gc * 128 + c16 * 8;
            cp_async16(abase + (uint32_t)(row * RS + c16 * 16), A + g, sz);
        }
    };

    const int l15   = lane & 15;
    const int aHalf = (lane & 16) ? 16 : 0;
    const uint32_t aRowOff0 = (uint32_t)((wm * 32 + l15) * RS + aHalf);
    const uint32_t aRowOff1 = aRowOff0 + 16 * RS;
    const int bRow  = (lane & 7) + ((lane & 16) ? 8 : 0);
    const int bHalf = (lane & 8) ? 16 : 0;
    uint32_t bRowByte[NT / 2];
    #pragma unroll
    for (int jp = 0; jp < NT / 2; jp++)
        bRowByte[jp] = (uint32_t)((wn * WN + jp * 16 + bRow) * RS + bHalf);

    int t0 = blockIdx.x;
    if (t0 < tiles) prefetch(t0, 0);
    CP_COMMIT();

    int it = 0;
    for (int t = t0; t < tiles; t += stride, it++) {
        const int buf = it & 1;
        int tn = t + stride;
        if (tn < tiles) prefetch(tn, buf ^ 1);
        CP_COMMIT();
        CP_WAIT1();
        __syncthreads();

        const uint32_t aB  = sb + OFF_A0 + buf * ABUF;

        float c[2][NT][4];
        #pragma unroll
        for (int mt = 0; mt < 2; mt++)
            #pragma unroll
            for (int j = 0; j < NT; j++)
                #pragma unroll
                for (int q = 0; q < 4; q++) c[mt][j][q] = 0.f;

        #pragma unroll
        for (int ks = 0; ks < 8; ks++) {
            const uint32_t kb = ks * 32;
            uint32_t a[2][4];
            ldsm4(aB + aRowOff0 + kb, a[0][0], a[0][1], a[0][2], a[0][3]);
            ldsm4(aB + aRowOff1 + kb, a[1][0], a[1][1], a[1][2], a[1][3]);
            uint32_t bh[NT][2], bl[NT][2];
            #pragma unroll
            for (int jp = 0; jp < NT / 2; jp++) {
                ldsm4(sb + bRowByte[jp] + kb,
                      bh[2 * jp][0], bh[2 * jp][1], bh[2 * jp + 1][0], bh[2 * jp + 1][1]);
                ldsm4(sb + OFF_WL + bRowByte[jp] + kb,
                      bl[2 * jp][0], bl[2 * jp][1], bl[2 * jp + 1][0], bl[2 * jp + 1][1]);
            }
            #pragma unroll
            for (int mt = 0; mt < 2; mt++)
                #pragma unroll
                for (int j = 0; j < NT; j++) {
                    mma_f16(c[mt][j], a[mt], bh[j][0], bh[j][1]);
                    mma_f16(c[mt][j], a[mt], bl[j][0], bl[j][1]);
                }
        }

        epilogue_store<WN, NT, CST>(c, C, t << 8, n, wm, wn, lane);
        __syncthreads();   // buf fully consumed before refill
    }
}

// ---------------- gather: packed f32x2 accumulation --------------------------
__global__ __launch_bounds__(256) void gather_h16_kernel(
    const __half* __restrict__ Y, const int* __restrict__ nbrs,
    __half* __restrict__ H, int n)
{
    const int warp = (blockIdx.x * blockDim.x + threadIdx.x) >> 5;
    const int lane = threadIdx.x & 31;
    if (warp >= n) return;

    int idx = 0;
    if (lane < SAMPLE) idx = nbrs[(size_t)warp * SAMPLE + lane];

    unsigned long long a01 = 0ull, a23 = 0ull;   // two packed f32x2 accumulators
    #pragma unroll
    for (int j = 0; j < SAMPLE; j++) {
        int row = __shfl_sync(0xffffffffu, idx, j);
        uint2 u = __ldg(reinterpret_cast<const uint2*>(Y + (size_t)row * 128) + lane);
        float2 f0 = __half22float2(*reinterpret_cast<__half2*>(&u.x));
        float2 f1 = __half22float2(*reinterpret_cast<__half2*>(&u.y));
        unsigned long long p0, p1;
        asm("mov.b64 %0, {%1, %2};" : "=l"(p0) : "f"(f0.x), "f"(f0.y));
        asm("mov.b64 %0, {%1, %2};" : "=l"(p1) : "f"(f1.x), "f"(f1.y));
        asm("add.rn.f32x2 %0, %0, %1;" : "+l"(a01) : "l"(p0));
        asm("add.rn.f32x2 %0, %0, %1;" : "+l"(a23) : "l"(p1));
    }
    float v0, v1, v2, v3;
    asm("mov.b64 {%0, %1}, %2;" : "=f"(v0), "=f"(v1) : "l"(a01));
    asm("mov.b64 {%0, %1}, %2;" : "=f"(v2), "=f"(v3) : "l"(a23));
    const float s = 1.0f / (float)SAMPLE;
    __half h[4] = { __float2half(fmaxf(v0 * s, 0.f)),
                    __float2half(fmaxf(v1 * s, 0.f)),
                    __float2half(fmaxf(v2 * s, 0.f)),
                    __float2half(fmaxf(v3 * s, 0.f)) };
    *(reinterpret_cast<uint2*>(H + (size_t)warp * 128) + lane) =
        *reinterpret_cast<uint2*>(h);
}

// ---------------- weight splitter (fp16 hi/lo) -------------------------------
__global__ void split_w_kernel(const float* __restrict__ W1,
                               const float* __restrict__ W2,
                               const float* __restrict__ WL,
                               __half* w1h, __half* w1l,
                               __half* w2h, __half* w2l,
                               __half* wlh, __half* wll)
{
    int i = blockIdx.x * blockDim.x + threadIdx.x;  // 0 .. 40959
    float v; __half *ph, *pl; int idx;
    if (i < 16384)      { v = W1[i];            ph = w1h; pl = w1l; idx = i; }
    else if (i < 32768) { idx = i - 16384; v = W2[idx]; ph = w2h; pl = w2l; }
    else if (i < 40960) {
        idx = i - 32768;                 // padded [64][128]
        int row = idx >> 7;
        v = (row < CLASSES) ? WL[idx] : 0.f;
        ph = wlh; pl = wll;
    } else return;
    __half h = __float2half(v);
    ph[idx] = h;
    pl[idx] = __float2half(v - __half2float(h));
}

// ================================================================
extern "C" void kernel_launch(void* const* d_in, const int* in_sizes, int n_in,
                              void* d_out, int out_size)
{
    const float* X    = (const float*)d_in[0];
    const int*   nbrs = (const int*)  d_in[1];
    const float* W1   = (const float*)d_in[2];
    const float* W2   = (const float*)d_in[3];
    const float* WL   = (const float*)d_in[4];
    float*       out  = (float*)d_out;
    const int n = in_sizes[1] / SAMPLE;

    __half *Y, *H, *w1h, *w1l, *w2h, *w2l, *wlh, *wll;
    cudaGetSymbolAddress((void**)&Y,   g_Y);
    cudaGetSymbolAddress((void**)&H,   g_H);
    cudaGetSymbolAddress((void**)&w1h, g_W1hi);
    cudaGetSymbolAddress((void**)&w1l, g_W1lo);
    cudaGetSymbolAddress((void**)&w2h, g_W2hi);
    cudaGetSymbolAddress((void**)&w2l, g_W2lo);
    cudaGetSymbolAddress((void**)&wlh, g_WLhi);
    cudaGetSymbolAddress((void**)&wll, g_WLlo);

    const int SMF   = RS * (128 + 2 * 128);           // 104448 (first gemm)
    const int SMP128 = RS * (2 * 128) + 2 * RS * 256; // 208896
    const int SMP64  = RS * (2 * 64)  + 2 * RS * 256; // 174080
    cudaFuncSetAttribute(gemm_first_kernel,
                         cudaFuncAttributeMaxDynamicSharedMemorySize, SMF);
    cudaFuncSetAttribute(gemm_pers_kernel<128, 128, __half>,
                         cudaFuncAttributeMaxDynamicSharedMemorySize, SMP128);
    cudaFuncSetAttribute(gemm_pers_kernel<64, 40, float>,
                         cudaFuncAttributeMaxDynamicSharedMemorySize, SMP64);

    const int gg = (n + 127) / 128;
    const int ag = (n + 7) / 8;

    split_w_kernel<<<160, 256>>>(W1, W2, WL, w1h, w1l, w2h, w2l, wlh, wll);
    gemm_first_kernel<<<gg, 256, SMF>>>(X, w1h, w1l, Y, n);
    gather_h16_kernel<<<ag, 256>>>(Y, nbrs, H, n);
    gemm_pers_kernel<128, 128, __half><<<NCTAS, 512, SMP128>>>(H, w2h, w2l, Y, n);
    gather_h16_kernel<<<ag, 256>>>(Y, nbrs, H, n);
    gemm_pers_kernel<64, 40, float><<<NCTAS, 512, SMP64>>>(H, wlh, wll, out, n);
}

// round 13
// speedup vs baseline: 1.1696x; 1.1696x over previous
#include <cuda_runtime.h>
#include <cuda_fp16.h>
#include <cstdint>

// ================================================================
// AutoGNN, 6 launches — single-plane fp16 weights (rn, err 2^-12):
//   1) w16:        W1/W2/WL -> fp16 (WL padded 40->64 rows)
//   2) gemm_first: Y = fp16(X) @ W1^T   (fp32 X converted in-register)
//   3) gather:     H = fp16(relu(mean(Y[nbrs])))   [packed f32x2 adds]
//   4) gemm_pers:  Y = H @ W2^T        [persistent, W resident, cp.async]
//   5) gather
//   6) gemm_pers<64,40>: out = H @ WL^T (fp32)
// GEMM: mma.sync m16n8k16 fp16, fp32 accum. Total rel_err ~4e-4.
// ================================================================

#define FEAT 128
#define SAMPLE 25
#define CLASSES 40
#define MAXN 100000
#define RS 272   // smem row stride bytes: conflict-free ldmatrix
#define NCTAS 152

__device__ __half g_Y[(size_t)MAXN * FEAT];
__device__ __half g_H[(size_t)MAXN * FEAT];
__device__ __half g_W1[128 * 128];
__device__ __half g_W2[128 * 128];
__device__ __half g_WL[64 * 128];

__device__ __forceinline__ uint32_t smem_u32(const void* p) {
    uint32_t a;
    asm("{ .reg .u64 t; cvta.to.shared.u64 t, %1; cvt.u32.u64 %0, t; }" : "=r"(a) : "l"(p));
    return a;
}
__device__ __forceinline__ void ldsm4(uint32_t addr, uint32_t& r0, uint32_t& r1,
                                      uint32_t& r2, uint32_t& r3) {
    asm volatile("ldmatrix.sync.aligned.m8n8.x4.shared.b16 {%0,%1,%2,%3}, [%4];"
                 : "=r"(r0), "=r"(r1), "=r"(r2), "=r"(r3) : "r"(addr));
}
__device__ __forceinline__ void mma_f16(float* c, const uint32_t* a,
                                        uint32_t b0, uint32_t b1) {
    asm volatile(
        "mma.sync.aligned.m16n8k16.row.col.f32.f16.f16.f32 "
        "{%0,%1,%2,%3}, {%4,%5,%6,%7}, {%8,%9}, {%0,%1,%2,%3};"
        : "+f"(c[0]), "+f"(c[1]), "+f"(c[2]), "+f"(c[3])
        : "r"(a[0]), "r"(a[1]), "r"(a[2]), "r"(a[3]), "r"(b0), "r"(b1));
}
__device__ __forceinline__ void cp_async16(uint32_t saddr, const void* gaddr,
                                           uint32_t src_sz) {
    asm volatile("cp.async.cg.shared.global [%0], [%1], 16, %2;"
                 :: "r"(saddr), "l"(gaddr), "r"(src_sz));
}
#define CP_COMMIT() asm volatile("cp.async.commit_group;" ::: "memory")
#define CP_WAIT1()  asm volatile("cp.async.wait_group 1;" ::: "memory")

// ---------------- shared epilogue helper -------------------------------------
template<int WN, int NT, int CST, typename TOUT>
__device__ __forceinline__ void epilogue_store(
    float c[2][NT][4], TOUT* __restrict__ C, int m0, int n,
    int wm, int wn, int lane)
{
    const int qrow = lane >> 2;
    const int qcol = (lane & 3) * 2;
    #pragma unroll
    for (int mt = 0; mt < 2; mt++) {
        #pragma unroll
        for (int half = 0; half < 2; half++) {
            int m_g = m0 + wm * 32 + mt * 16 + qrow + half * 8;
            if (m_g < n) {
                TOUT* crow = C + (size_t)m_g * CST;
                #pragma unroll
                for (int j = 0; j < NT; j++) {
                    int n_g = wn * WN + j * 8 + qcol;
                    if (CST == 128 || n_g < CST) {
                        float v0 = c[mt][j][half * 2];
                        float v1 = c[mt][j][half * 2 + 1];
                        if constexpr (sizeof(TOUT) == 2) {
                            __half2 hv = __floats2half2_rn(v0, v1);
                            *reinterpret_cast<__half2*>(crow + n_g) = hv;
                        } else {
                            *reinterpret_cast<float2*>(crow + n_g) =
                                make_float2(v0, v1);
                        }
                    }
                }
            }
        }
    }
}

// ================================================================
// kernel 2: Y(fp16) = fp16(X) @ W1^T — 8 warps, CTA tile 128x128.
// smem: [A 128*RS][W 128*RS] = 69.6 KB -> 2+ CTAs/SM.
// ================================================================
__global__ __launch_bounds__(256, 2) void gemm_first_kernel(
    const float* __restrict__ X, const __half* __restrict__ W,
    __half* __restrict__ C, int n)
{
    extern __shared__ char smem[];
    constexpr int OFF_W = 128 * RS;
    const int tid  = threadIdx.x;
    const int wid  = tid >> 5;
    const int lane = tid & 31;
    const int wm   = wid >> 1;
    const int wn   = wid & 1;
    const int m0   = blockIdx.x * 128;

    #pragma unroll
    for (int i = 0; i < 16; i++) {
        int t = i * 256 + tid;              // 4096 float4
        int row = t >> 5;
        int c4  = t & 31;
        int grow = m0 + row;
        float4 v = make_float4(0.f, 0.f, 0.f, 0.f);
        if (grow < n)
            v = __ldg(reinterpret_cast<const float4*>(X + (size_t)grow * 128) + c4);
        __half h[4] = { __float2half(v.x), __float2half(v.y),
                        __float2half(v.z), __float2half(v.w) };
        *reinterpret_cast<uint2*>(smem + row * RS + c4 * 8) =
            *reinterpret_cast<uint2*>(h);
    }
    #pragma unroll
    for (int i = 0; i < 8; i++) {
        int t = i * 256 + tid;
        int row = t >> 4;
        int c16 = t & 15;
        *reinterpret_cast<uint4*>(smem + OFF_W + row * RS + c16 * 16) =
            *reinterpret_cast<const uint4*>(W + (size_t)row * 128 + c16 * 8);
    }
    __syncthreads();

    const uint32_t sb = smem_u32(smem);
    const int l15   = lane & 15;
    const int aHalf = (lane & 16) ? 16 : 0;
    const uint32_t aRow0 = (uint32_t)((wm * 32 + l15) * RS + aHalf);
    const uint32_t aRow1 = aRow0 + 16 * RS;
    const int bRow  = (lane & 7) + ((lane & 16) ? 8 : 0);
    const int bHalf = (lane & 8) ? 16 : 0;
    uint32_t bRowByte[4];
    #pragma unroll
    for (int jp = 0; jp < 4; jp++)
        bRowByte[jp] = (uint32_t)((wn * 64 + jp * 16 + bRow) * RS + bHalf);

    float c[2][8][4];
    #pragma unroll
    for (int mt = 0; mt < 2; mt++)
        #pragma unroll
        for (int j = 0; j < 8; j++)
            #pragma unroll
            for (int q = 0; q < 4; q++) c[mt][j][q] = 0.f;

    #pragma unroll
    for (int ks = 0; ks < 8; ks++) {
        const uint32_t kb = ks * 32;
        uint32_t a[2][4];
        ldsm4(sb + aRow0 + kb, a[0][0], a[0][1], a[0][2], a[0][3]);
        ldsm4(sb + aRow1 + kb, a[1][0], a[1][1], a[1][2], a[1][3]);
        uint32_t b[8][2];
        #pragma unroll
        for (int jp = 0; jp < 4; jp++)
            ldsm4(sb + OFF_W + bRowByte[jp] + kb,
                  b[2 * jp][0], b[2 * jp][1], b[2 * jp + 1][0], b[2 * jp + 1][1]);
        #pragma unroll
        for (int mt = 0; mt < 2; mt++)
            #pragma unroll
            for (int j = 0; j < 8; j++)
                mma_f16(c[mt][j], a[mt], b[j][0], b[j][1]);
    }
    epilogue_store<64, 8, 128>(c, C, m0, n, wm, wn, lane);
}

// ================================================================
// kernels 4/6: persistent GEMM, W resident, A cp.async double-buffered.
// CTA tile 256 x NOUT, 512 threads / 16 warps.
// smem: [W NOUT*RS][Abuf0 256*RS][Abuf1 256*RS]
// ================================================================
template<int NOUT, int CST, typename TOUT>
__global__ __launch_bounds__(512, 1) void gemm_pers_kernel(
    const __half* __restrict__ A, const __half* __restrict__ W,
    TOUT* __restrict__ C, int n)
{
    extern __shared__ char smem[];
    constexpr int OFF_A0 = NOUT * RS;
    constexpr int ABUF   = 256 * RS;
    constexpr int WN = NOUT / 2;
    constexpr int NT = WN / 8;

    const int tid  = threadIdx.x;
    const int wid  = tid >> 5;
    const int lane = tid & 31;
    const int wm   = wid >> 1;         // 0..7
    const int wn   = wid & 1;          // 0..1
    const uint32_t sb = smem_u32(smem);

    #pragma unroll
    for (int i = 0; i < NOUT / 32; i++) {
        int t = i * 512 + tid;
        int row = t >> 4;
        int c16 = t & 15;
        *reinterpret_cast<uint4*>(smem + row * RS + c16 * 16) =
            *reinterpret_cast<const uint4*>(W + (size_t)row * 128 + c16 * 8);
    }

    const int tiles  = (n + 255) >> 8;
    const int stride = gridDim.x;

    auto prefetch = [&](int t, int buf) {
        const uint32_t abase = sb + OFF_A0 + buf * ABUF;
        const int m0 = t << 8;
        #pragma unroll
        for (int i = 0; i < 8; i++) {
            int k = i * 512 + tid;
            int row = k >> 4;
            int c16 = k & 15;
            int grow = m0 + row;
            uint32_t sz = (grow < n) ? 16u : 0u;
            int gc = (grow < n) ? grow : 0;
            size_t g = (size_t)gc * 128 + c16 * 8;
            cp_async16(abase + (uint32_t)(row * RS + c16 * 16), A + g, sz);
        }
    };

    const int l15   = lane & 15;
    const int aHalf = (lane & 16) ? 16 : 0;
    const uint32_t aRowOff0 = (uint32_t)((wm * 32 + l15) * RS + aHalf);
    const uint32_t aRowOff1 = aRowOff0 + 16 * RS;
    const int bRow  = (lane & 7) + ((lane & 16) ? 8 : 0);
    const int bHalf = (lane & 8) ? 16 : 0;
    uint32_t bRowByte[NT / 2];
    #pragma unroll
    for (int jp = 0; jp < NT / 2; jp++)
        bRowByte[jp] = (uint32_t)((wn * WN + jp * 16 + bRow) * RS + bHalf);

    int t0 = blockIdx.x;
    if (t0 < tiles) prefetch(t0, 0);
    CP_COMMIT();

    int it = 0;
    for (int t = t0; t < tiles; t += stride, it++) {
        const int buf = it & 1;
        int tn = t + stride;
        if (tn < tiles) prefetch(tn, buf ^ 1);
        CP_COMMIT();
        CP_WAIT1();
        __syncthreads();

        const uint32_t aB = sb + OFF_A0 + buf * ABUF;

        float c[2][NT][4];
        #pragma unroll
        for (int mt = 0; mt < 2; mt++)
            #pragma unroll
            for (int j = 0; j < NT; j++)
                #pragma unroll
                for (int q = 0; q < 4; q++) c[mt][j][q] = 0.f;

        #pragma unroll
        for (int ks = 0; ks < 8; ks++) {
            const uint32_t kb = ks * 32;
            uint32_t a[2][4];
            ldsm4(aB + aRowOff0 + kb, a[0][0], a[0][1], a[0][2], a[0][3]);
            ldsm4(aB + aRowOff1 + kb, a[1][0], a[1][1], a[1][2], a[1][3]);
            uint32_t b[NT][2];
            #pragma unroll
            for (int jp = 0; jp < NT / 2; jp++)
                ldsm4(sb + bRowByte[jp] + kb,
                      b[2 * jp][0], b[2 * jp][1], b[2 * jp + 1][0], b[2 * jp + 1][1]);
            #pragma unroll
            for (int mt = 0; mt < 2; mt++)
                #pragma unroll
                for (int j = 0; j < NT; j++)
                    mma_f16(c[mt][j], a[mt], b[j][0], b[j][1]);
        }

        epilogue_store<WN, NT, CST>(c, C, t << 8, n, wm, wn, lane);
        __syncthreads();   // buf fully consumed before refill
    }
}

// ---------------- gather: packed f32x2 accumulation --------------------------
__global__ __launch_bounds__(256) void gather_h16_kernel(
    const __half* __restrict__ Y, const int* __restrict__ nbrs,
    __half* __restrict__ H, int n)
{
    const int warp = (blockIdx.x * blockDim.x + threadIdx.x) >> 5;
    const int lane = threadIdx.x & 31;
    if (warp >= n) return;

    int idx = 0;
    if (lane < SAMPLE) idx = nbrs[(size_t)warp * SAMPLE + lane];

    unsigned long long a01 = 0ull, a23 = 0ull;
    #pragma unroll
    for (int j = 0; j < SAMPLE; j++) {
        int row = __shfl_sync(0xffffffffu, idx, j);
        uint2 u = __ldg(reinterpret_cast<const uint2*>(Y + (size_t)row * 128) + lane);
        float2 f0 = __half22float2(*reinterpret_cast<__half2*>(&u.x));
        float2 f1 = __half22float2(*reinterpret_cast<__half2*>(&u.y));
        unsigned long long p0, p1;
        asm("mov.b64 %0, {%1, %2};" : "=l"(p0) : "f"(f0.x), "f"(f0.y));
        asm("mov.b64 %0, {%1, %2};" : "=l"(p1) : "f"(f1.x), "f"(f1.y));
        asm("add.rn.f32x2 %0, %0, %1;" : "+l"(a01) : "l"(p0));
        asm("add.rn.f32x2 %0, %0, %1;" : "+l"(a23) : "l"(p1));
    }
    float v0, v1, v2, v3;
    asm("mov.b64 {%0, %1}, %2;" : "=f"(v0), "=f"(v1) : "l"(a01));
    asm("mov.b64 {%0, %1}, %2;" : "=f"(v2), "=f"(v3) : "l"(a23));
    const float s = 1.0f / (float)SAMPLE;
    __half h[4] = { __float2half(fmaxf(v0 * s, 0.f)),
                    __float2half(fmaxf(v1 * s, 0.f)),
                    __float2half(fmaxf(v2 * s, 0.f)),
                    __float2half(fmaxf(v3 * s, 0.f)) };
    *(reinterpret_cast<uint2*>(H + (size_t)warp * 128) + lane) =
        *reinterpret_cast<uint2*>(h);
}

// ---------------- kernel 1: W -> fp16 (rn) -----------------------------------
__global__ void w16_kernel(const float* __restrict__ W1,
                           const float* __restrict__ W2,
                           const float* __restrict__ WL,
                           __half* w1, __half* w2, __half* wl)
{
    int i = blockIdx.x * blockDim.x + threadIdx.x;  // 0 .. 40959
    if (i < 16384)      w1[i] = __float2half(W1[i]);
    else if (i < 32768) { int k = i - 16384; w2[k] = __float2half(W2[k]); }
    else if (i < 40960) {
        int k = i - 32768;                // padded [64][128]
        int row = k >> 7;
        wl[k] = __float2half((row < CLASSES) ? WL[k] : 0.f);
    }
}

// ================================================================
extern "C" void kernel_launch(void* const* d_in, const int* in_sizes, int n_in,
                              void* d_out, int out_size)
{
    const float* X    = (const float*)d_in[0];
    const int*   nbrs = (const int*)  d_in[1];
    const float* W1   = (const float*)d_in[2];
    const float* W2   = (const float*)d_in[3];
    const float* WL   = (const float*)d_in[4];
    float*       out  = (float*)d_out;
    const int n = in_sizes[1] / SAMPLE;

    __half *Y, *H, *w1, *w2, *wl;
    cudaGetSymbolAddress((void**)&Y,  g_Y);
    cudaGetSymbolAddress((void**)&H,  g_H);
    cudaGetSymbolAddress((void**)&w1, g_W1);
    cudaGetSymbolAddress((void**)&w2, g_W2);
    cudaGetSymbolAddress((void**)&wl, g_WL);

    const int SMF    = RS * (128 + 128);          //  69632 (first gemm)
    const int SMP128 = RS * 128 + 2 * RS * 256;   // 174080
    const int SMP64  = RS * 64  + 2 * RS * 256;   // 156672
    cudaFuncSetAttribute(gemm_first_kernel,
                         cudaFuncAttributeMaxDynamicSharedMemorySize, SMF);
    cudaFuncSetAttribute(gemm_pers_kernel<128, 128, __half>,
                         cudaFuncAttributeMaxDynamicSharedMemorySize, SMP128);
    cudaFuncSetAttribute(gemm_pers_kernel<64, 40, float>,
                         cudaFuncAttributeMaxDynamicSharedMemorySize, SMP64);

    const int gg = (n + 127) / 128;
    const int ag = (n + 7) / 8;

    w16_kernel<<<160, 256>>>(W1, W2, WL, w1, w2, wl);
    gemm_first_kernel<<<gg, 256, SMF>>>(X, w1, Y, n);
    gather_h16_kernel<<<ag, 256>>>(Y, nbrs, H, n);
    gemm_pers_kernel<128, 128, __half><<<NCTAS, 512, SMP128>>>(H, w2, Y, n);
    gather_h16_kernel<<<ag, 256>>>(Y, nbrs, H, n);
    gemm_pers_kernel<64, 40, float><<<NCTAS, 512, SMP64>>>(H, wl, out, n);
}

// round 14
// speedup vs baseline: 1.3003x; 1.1118x over previous
#include <cuda_runtime.h>
#include <cuda_fp16.h>
#include <cstdint>

// ================================================================
// AutoGNN, 6 launches — single-plane fp16 weights, fp16 pairwise
// first-level gather adds:
//   1) w16:        W1/W2/WL -> fp16 (WL padded 40->64 rows)
//   2) gemm_first: Y = fp16(X) @ W1^T   (fp32 X converted in-register)
//   3) gather:     H = fp16(relu(mean(Y[nbrs]))) [HADD2 pairs -> f32]
//   4) gemm_pers:  Y = H @ W2^T        [persistent, W resident, cp.async]
//   5) gather
//   6) gemm_pers<64,40>: out = H @ WL^T (fp32)
// GEMM: mma.sync m16n8k16 fp16, fp32 accum. Total rel_err ~6e-4.
// ================================================================

#define FEAT 128
#define SAMPLE 25
#define CLASSES 40
#define MAXN 100000
#define RS 272   // smem row stride bytes: conflict-free ldmatrix
#define NCTAS 152

__device__ __half g_Y[(size_t)MAXN * FEAT];
__device__ __half g_H[(size_t)MAXN * FEAT];
__device__ __half g_W1[128 * 128];
__device__ __half g_W2[128 * 128];
__device__ __half g_WL[64 * 128];

__device__ __forceinline__ uint32_t smem_u32(const void* p) {
    uint32_t a;
    asm("{ .reg .u64 t; cvta.to.shared.u64 t, %1; cvt.u32.u64 %0, t; }" : "=r"(a) : "l"(p));
    return a;
}
__device__ __forceinline__ void ldsm4(uint32_t addr, uint32_t& r0, uint32_t& r1,
                                      uint32_t& r2, uint32_t& r3) {
    asm volatile("ldmatrix.sync.aligned.m8n8.x4.shared.b16 {%0,%1,%2,%3}, [%4];"
                 : "=r"(r0), "=r"(r1), "=r"(r2), "=r"(r3) : "r"(addr));
}
__device__ __forceinline__ void mma_f16(float* c, const uint32_t* a,
                                        uint32_t b0, uint32_t b1) {
    asm volatile(
        "mma.sync.aligned.m16n8k16.row.col.f32.f16.f16.f32 "
        "{%0,%1,%2,%3}, {%4,%5,%6,%7}, {%8,%9}, {%0,%1,%2,%3};"
        : "+f"(c[0]), "+f"(c[1]), "+f"(c[2]), "+f"(c[3])
        : "r"(a[0]), "r"(a[1]), "r"(a[2]), "r"(a[3]), "r"(b0), "r"(b1));
}
__device__ __forceinline__ void cp_async16(uint32_t saddr, const void* gaddr,
                                           uint32_t src_sz) {
    asm volatile("cp.async.cg.shared.global [%0], [%1], 16, %2;"
                 :: "r"(saddr), "l"(gaddr), "r"(src_sz));
}
#define CP_COMMIT() asm volatile("cp.async.commit_group;" ::: "memory")
#define CP_WAIT1()  asm volatile("cp.async.wait_group 1;" ::: "memory")

// ---------------- shared epilogue helper -------------------------------------
template<int WN, int NT, int CST, typename TOUT>
__device__ __forceinline__ void epilogue_store(
    float c[2][NT][4], TOUT* __restrict__ C, int m0, int n,
    int wm, int wn, int lane)
{
    const int qrow = lane >> 2;
    const int qcol = (lane & 3) * 2;
    #pragma unroll
    for (int mt = 0; mt < 2; mt++) {
        #pragma unroll
        for (int half = 0; half < 2; half++) {
            int m_g = m0 + wm * 32 + mt * 16 + qrow + half * 8;
            if (m_g < n) {
                TOUT* crow = C + (size_t)m_g * CST;
                #pragma unroll
                for (int j = 0; j < NT; j++) {
                    int n_g = wn * WN + j * 8 + qcol;
                    if (CST == 128 || n_g < CST) {
                        float v0 = c[mt][j][half * 2];
                        float v1 = c[mt][j][half * 2 + 1];
                        if constexpr (sizeof(TOUT) == 2) {
                            __half2 hv = __floats2half2_rn(v0, v1);
                            *reinterpret_cast<__half2*>(crow + n_g) = hv;
                        } else {
                            *reinterpret_cast<float2*>(crow + n_g) =
                                make_float2(v0, v1);
                        }
                    }
                }
            }
        }
    }
}

// ================================================================
// kernel 2: Y(fp16) = fp16(X) @ W1^T — 8 warps, CTA tile 128x128.
// smem: [A 128*RS][W 128*RS] = 69.6 KB -> 2+ CTAs/SM.
// ================================================================
__global__ __launch_bounds__(256, 2) void gemm_first_kernel(
    const float* __restrict__ X, const __half* __restrict__ W,
    __half* __restrict__ C, int n)
{
    extern __shared__ char smem[];
    constexpr int OFF_W = 128 * RS;
    const int tid  = threadIdx.x;
    const int wid  = tid >> 5;
    const int lane = tid & 31;
    const int wm   = wid >> 1;
    const int wn   = wid & 1;
    const int m0   = blockIdx.x * 128;

    #pragma unroll
    for (int i = 0; i < 16; i++) {
        int t = i * 256 + tid;              // 4096 float4
        int row = t >> 5;
        int c4  = t & 31;
        int grow = m0 + row;
        float4 v = make_float4(0.f, 0.f, 0.f, 0.f);
        if (grow < n)
            v = __ldg(reinterpret_cast<const float4*>(X + (size_t)grow * 128) + c4);
        __half h[4] = { __float2half(v.x), __float2half(v.y),
                        __float2half(v.z), __float2half(v.w) };
        *reinterpret_cast<uint2*>(smem + row * RS + c4 * 8) =
            *reinterpret_cast<uint2*>(h);
    }
    #pragma unroll
    for (int i = 0; i < 8; i++) {
        int t = i * 256 + tid;
        int row = t >> 4;
        int c16 = t & 15;
        *reinterpret_cast<uint4*>(smem + OFF_W + row * RS + c16 * 16) =
            *reinterpret_cast<const uint4*>(W + (size_t)row * 128 + c16 * 8);
    }
    __syncthreads();

    const uint32_t sb = smem_u32(smem);
    const int l15   = lane & 15;
    const int aHalf = (lane & 16) ? 16 : 0;
    const uint32_t aRow0 = (uint32_t)((wm * 32 + l15) * RS + aHalf);
    const uint32_t aRow1 = aRow0 + 16 * RS;
    const int bRow  = (lane & 7) + ((lane & 16) ? 8 : 0);
    const int bHalf = (lane & 8) ? 16 : 0;
    uint32_t bRowByte[4];
    #pragma unroll
    for (int jp = 0; jp < 4; jp++)
        bRowByte[jp] = (uint32_t)((wn * 64 + jp * 16 + bRow) * RS + bHalf);

    float c[2][8][4];
    #pragma unroll
    for (int mt = 0; mt < 2; mt++)
        #pragma unroll
        for (int j = 0; j < 8; j++)
            #pragma unroll
            for (int q = 0; q < 4; q++) c[mt][j][q] = 0.f;

    #pragma unroll
    for (int ks = 0; ks < 8; ks++) {
        const uint32_t kb = ks * 32;
        uint32_t a[2][4];
        ldsm4(sb + aRow0 + kb, a[0][0], a[0][1], a[0][2], a[0][3]);
        ldsm4(sb + aRow1 + kb, a[1][0], a[1][1], a[1][2], a[1][3]);
        uint32_t b[8][2];
        #pragma unroll
        for (int jp = 0; jp < 4; jp++)
            ldsm4(sb + OFF_W + bRowByte[jp] + kb,
                  b[2 * jp][0], b[2 * jp][1], b[2 * jp + 1][0], b[2 * jp + 1][1]);
        #pragma unroll
        for (int mt = 0; mt < 2; mt++)
            #pragma unroll
            for (int j = 0; j < 8; j++)
                mma_f16(c[mt][j], a[mt], b[j][0], b[j][1]);
    }
    epilogue_store<64, 8, 128>(c, C, m0, n, wm, wn, lane);
}

// ================================================================
// kernels 4/6: persistent GEMM, W resident, A cp.async double-buffered.
// CTA tile 256 x NOUT, 512 threads / 16 warps.
// smem: [W NOUT*RS][Abuf0 256*RS][Abuf1 256*RS]
// ================================================================
template<int NOUT, int CST, typename TOUT>
__global__ __launch_bounds__(512, 1) void gemm_pers_kernel(
    const __half* __restrict__ A, const __half* __restrict__ W,
    TOUT* __restrict__ C, int n)
{
    extern __shared__ char smem[];
    constexpr int OFF_A0 = NOUT * RS;
    constexpr int ABUF   = 256 * RS;
    constexpr int WN = NOUT / 2;
    constexpr int NT = WN / 8;

    const int tid  = threadIdx.x;
    const int wid  = tid >> 5;
    const int lane = tid & 31;
    const int wm   = wid >> 1;         // 0..7
    const int wn   = wid & 1;          // 0..1
    const uint32_t sb = smem_u32(smem);

    #pragma unroll
    for (int i = 0; i < NOUT / 32; i++) {
        int t = i * 512 + tid;
        int row = t >> 4;
        int c16 = t & 15;
        *reinterpret_cast<uint4*>(smem + row * RS + c16 * 16) =
            *reinterpret_cast<const uint4*>(W + (size_t)row * 128 + c16 * 8);
    }

    const int tiles  = (n + 255) >> 8;
    const int stride = gridDim.x;

    auto prefetch = [&](int t, int buf) {
        const uint32_t abase = sb + OFF_A0 + buf * ABUF;
        const int m0 = t << 8;
        #pragma unroll
        for (int i = 0; i < 8; i++) {
            int k = i * 512 + tid;
            int row = k >> 4;
            int c16 = k & 15;
            int grow = m0 + row;
            uint32_t sz = (grow < n) ? 16u : 0u;
            int gc = (grow < n) ? grow : 0;
            size_t g = (size_t)gc * 128 + c16 * 8;
            cp_async16(abase + (uint32_t)(row * RS + c16 * 16), A + g, sz);
        }
    };

    const int l15   = lane & 15;
    const int aHalf = (lane & 16) ? 16 : 0;
    const uint32_t aRowOff0 = (uint32_t)((wm * 32 + l15) * RS + aHalf);
    const uint32_t aRowOff1 = aRowOff0 + 16 * RS;
    const int bRow  = (lane & 7) + ((lane & 16) ? 8 : 0);
    const int bHalf = (lane & 8) ? 16 : 0;
    uint32_t bRowByte[NT / 2];
    #pragma unroll
    for (int jp = 0; jp < NT / 2; jp++)
        bRowByte[jp] = (uint32_t)((wn * WN + jp * 16 + bRow) * RS + bHalf);

    int t0 = blockIdx.x;
    if (t0 < tiles) prefetch(t0, 0);
    CP_COMMIT();

    int it = 0;
    for (int t = t0; t < tiles; t += stride, it++) {
        const int buf = it & 1;
        int tn = t + stride;
        if (tn < tiles) prefetch(tn, buf ^ 1);
        CP_COMMIT();
        CP_WAIT1();
        __syncthreads();

        const uint32_t aB = sb + OFF_A0 + buf * ABUF;

        float c[2][NT][4];
        #pragma unroll
        for (int mt = 0; mt < 2; mt++)
            #pragma unroll
            for (int j = 0; j < NT; j++)
                #pragma unroll
                for (int q = 0; q < 4; q++) c[mt][j][q] = 0.f;

        #pragma unroll
        for (int ks = 0; ks < 8; ks++) {
            const uint32_t kb = ks * 32;
            uint32_t a[2][4];
            ldsm4(aB + aRowOff0 + kb, a[0][0], a[0][1], a[0][2], a[0][3]);
            ldsm4(aB + aRowOff1 + kb, a[1][0], a[1][1], a[1][2], a[1][3]);
            uint32_t b[NT][2];
            #pragma unroll
            for (int jp = 0; jp < NT / 2; jp++)
                ldsm4(sb + bRowByte[jp] + kb,
                      b[2 * jp][0], b[2 * jp][1], b[2 * jp + 1][0], b[2 * jp + 1][1]);
            #pragma unroll
            for (int mt = 0; mt < 2; mt++)
                #pragma unroll
                for (int j = 0; j < NT; j++)
                    mma_f16(c[mt][j], a[mt], b[j][0], b[j][1]);
        }

        epilogue_store<WN, NT, CST>(c, C, t << 8, n, wm, wn, lane);
        __syncthreads();   // buf fully consumed before refill
    }
}

// ---------------- gather: HADD2 pairs -> fp32 accumulation -------------------
__global__ __launch_bounds__(256) void gather_h16_kernel(
    const __half* __restrict__ Y, const int* __restrict__ nbrs,
    __half* __restrict__ H, int n)
{
    const int warp = (blockIdx.x * blockDim.x + threadIdx.x) >> 5;
    const int lane = threadIdx.x & 31;
    if (warp >= n) return;

    int idx = 0;
    if (lane < SAMPLE) idx = nbrs[(size_t)warp * SAMPLE + lane];

    float a0 = 0.f, a1 = 0.f, a2 = 0.f, a3 = 0.f;
    // 12 pairs: fp16 pairwise add, then fp32 accumulate
    #pragma unroll
    for (int jp = 0; jp < SAMPLE / 2; jp++) {
        int r0 = __shfl_sync(0xffffffffu, idx, 2 * jp);
        int r1 = __shfl_sync(0xffffffffu, idx, 2 * jp + 1);
        uint2 u0 = __ldg(reinterpret_cast<const uint2*>(Y + (size_t)r0 * 128) + lane);
        uint2 u1 = __ldg(reinterpret_cast<const uint2*>(Y + (size_t)r1 * 128) + lane);
        __half2 s0 = __hadd2(*reinterpret_cast<__half2*>(&u0.x),
                             *reinterpret_cast<__half2*>(&u1.x));
        __half2 s1 = __hadd2(*reinterpret_cast<__half2*>(&u0.y),
                             *reinterpret_cast<__half2*>(&u1.y));
        float2 f0 = __half22float2(s0);
        float2 f1 = __half22float2(s1);
        a0 += f0.x; a1 += f0.y; a2 += f1.x; a3 += f1.y;
    }
    // last (odd) sample
    {
        int r = __shfl_sync(0xffffffffu, idx, SAMPLE - 1);
        uint2 u = __ldg(reinterpret_cast<const uint2*>(Y + (size_t)r * 128) + lane);
        float2 f0 = __half22float2(*reinterpret_cast<__half2*>(&u.x));
        float2 f1 = __half22float2(*reinterpret_cast<__half2*>(&u.y));
        a0 += f0.x; a1 += f0.y; a2 += f1.x; a3 += f1.y;
    }
    const float s = 1.0f / (float)SAMPLE;
    __half h[4] = { __float2half(fmaxf(a0 * s, 0.f)),
                    __float2half(fmaxf(a1 * s, 0.f)),
                    __float2half(fmaxf(a2 * s, 0.f)),
                    __float2half(fmaxf(a3 * s, 0.f)) };
    *(reinterpret_cast<uint2*>(H + (size_t)warp * 128) + lane) =
        *reinterpret_cast<uint2*>(h);
}

// ---------------- kernel 1: W -> fp16 (rn) -----------------------------------
__global__ void w16_kernel(const float* __restrict__ W1,
                           const float* __restrict__ W2,
                           const float* __restrict__ WL,
                           __half* w1, __half* w2, __half* wl)
{
    int i = blockIdx.x * blockDim.x + threadIdx.x;  // 0 .. 40959
    if (i < 16384)      w1[i] = __float2half(W1[i]);
    else if (i < 32768) { int k = i - 16384; w2[k] = __float2half(W2[k]); }
    else if (i < 40960) {
        int k = i - 32768;                // padded [64][128]
        int row = k >> 7;
        wl[k] = __float2half((row < CLASSES) ? WL[k] : 0.f);
    }
}

// ================================================================
extern "C" void kernel_launch(void* const* d_in, const int* in_sizes, int n_in,
                              void* d_out, int out_size)
{
    const float* X    = (const float*)d_in[0];
    const int*   nbrs = (const int*)  d_in[1];
    const float* W1   = (const float*)d_in[2];
    const float* W2   = (const float*)d_in[3];
    const float* WL   = (const float*)d_in[4];
    float*       out  = (float*)d_out;
    const int n = in_sizes[1] / SAMPLE;

    __half *Y, *H, *w1, *w2, *wl;
    cudaGetSymbolAddress((void**)&Y,  g_Y);
    cudaGetSymbolAddress((void**)&H,  g_H);
    cudaGetSymbolAddress((void**)&w1, g_W1);
    cudaGetSymbolAddress((void**)&w2, g_W2);
    cudaGetSymbolAddress((void**)&wl, g_WL);

    const int SMF    = RS * (128 + 128);          //  69632 (first gemm)
    const int SMP128 = RS * 128 + 2 * RS * 256;   // 174080
    const int SMP64  = RS * 64  + 2 * RS * 256;   // 156672
    cudaFuncSetAttribute(gemm_first_kernel,
                         cudaFuncAttributeMaxDynamicSharedMemorySize, SMF);
    cudaFuncSetAttribute(gemm_pers_kernel<128, 128, __half>,
                         cudaFuncAttributeMaxDynamicSharedMemorySize, SMP128);
    cudaFuncSetAttribute(gemm_pers_kernel<64, 40, float>,
                         cudaFuncAttributeMaxDynamicSharedMemorySize, SMP64);

    const int gg = (n + 127) / 128;
    const int ag = (n + 7) / 8;

    w16_kernel<<<160, 256>>>(W1, W2, WL, w1, w2, wl);
    gemm_first_kernel<<<gg, 256, SMF>>>(X, w1, Y, n);
    gather_h16_kernel<<<ag, 256>>>(Y, nbrs, H, n);
    gemm_pers_kernel<128, 128, __half><<<NCTAS, 512, SMP128>>>(H, w2, Y, n);
    gather_h16_kernel<<<ag, 256>>>(Y, nbrs, H, n);
    gemm_pers_kernel<64, 40, float><<<NCTAS, 512, SMP64>>>(H, wl, out, n);
}

// round 15
// speedup vs baseline: 1.3006x; 1.0003x over previous
#include <cuda_runtime.h>
#include <cuda_fp16.h>
#include <cstdint>

// ================================================================
// AutoGNN, 5 launches — fp16 weights converted in-kernel:
//   1) gemm_first: Y = fp16(X) @ fp16(W1)^T   (all converts in-register)
//   2) gather:     H = fp16(relu(mean(Y[nbrs]))) [HADD2 pairs -> f32]
//   3) gemm_pers:  Y = H @ fp16(W2)^T  [persistent, 2 CTAs/SM, cp.async]
//   4) gather
//   5) gemm_pers<64,40>: out = H @ fp16(WL)^T (fp32)
// GEMM: mma.sync m16n8k16 fp16, fp32 accum. rel_err ~4.6e-4.
// ================================================================

#define FEAT 128
#define SAMPLE 25
#define CLASSES 40
#define MAXN 100000
#define RS 272   // smem row stride bytes: conflict-free ldmatrix
#define NPERS 304   // 2 CTAs per SM (152 SMs)

__device__ __half g_Y[(size_t)MAXN * FEAT];
__device__ __half g_H[(size_t)MAXN * FEAT];

__device__ __forceinline__ uint32_t smem_u32(const void* p) {
    uint32_t a;
    asm("{ .reg .u64 t; cvta.to.shared.u64 t, %1; cvt.u32.u64 %0, t; }" : "=r"(a) : "l"(p));
    return a;
}
__device__ __forceinline__ void ldsm4(uint32_t addr, uint32_t& r0, uint32_t& r1,
                                      uint32_t& r2, uint32_t& r3) {
    asm volatile("ldmatrix.sync.aligned.m8n8.x4.shared.b16 {%0,%1,%2,%3}, [%4];"
                 : "=r"(r0), "=r"(r1), "=r"(r2), "=r"(r3) : "r"(addr));
}
__device__ __forceinline__ void mma_f16(float* c, const uint32_t* a,
                                        uint32_t b0, uint32_t b1) {
    asm volatile(
        "mma.sync.aligned.m16n8k16.row.col.f32.f16.f16.f32 "
        "{%0,%1,%2,%3}, {%4,%5,%6,%7}, {%8,%9}, {%0,%1,%2,%3};"
        : "+f"(c[0]), "+f"(c[1]), "+f"(c[2]), "+f"(c[3])
        : "r"(a[0]), "r"(a[1]), "r"(a[2]), "r"(a[3]), "r"(b0), "r"(b1));
}
__device__ __forceinline__ void cp_async16(uint32_t saddr, const void* gaddr,
                                           uint32_t src_sz) {
    asm volatile("cp.async.cg.shared.global [%0], [%1], 16, %2;"
                 :: "r"(saddr), "l"(gaddr), "r"(src_sz));
}
#define CP_COMMIT() asm volatile("cp.async.commit_group;" ::: "memory")
#define CP_WAIT1()  asm volatile("cp.async.wait_group 1;" ::: "memory")

// ---- W loader: fp32 gmem -> fp16 smem (NOUT rows x 128), 256 threads,
//      WL padding handled by row<CLASSES ? W : 0 (PADC template arg) ----
template<int NOUT, int PADC>
__device__ __forceinline__ void load_w_cvt(
    char* smem, int woff, const float* __restrict__ W)
{
    const int tid = threadIdx.x;
    #pragma unroll
    for (int i = 0; i < NOUT / 8; i++) {
        int t = i * 256 + tid;             // NOUT*32 float4s
        int row = t >> 5;
        int c4  = t & 31;
        float4 v = make_float4(0.f, 0.f, 0.f, 0.f);
        if (PADC == 0 || row < PADC)
            v = __ldg(reinterpret_cast<const float4*>(W + (size_t)row * 128) + c4);
        __half h[4] = { __float2half(v.x), __float2half(v.y),
                        __float2half(v.z), __float2half(v.w) };
        *reinterpret_cast<uint2*>(smem + woff + row * RS + c4 * 8) =
            *reinterpret_cast<uint2*>(h);
    }
}

// ---------------- shared epilogue helper -------------------------------------
template<int WN, int NT, int CST, typename TOUT>
__device__ __forceinline__ void epilogue_store(
    float c[2][NT][4], TOUT* __restrict__ C, int m0, int n,
    int wm, int wn, int lane)
{
    const int qrow = lane >> 2;
    const int qcol = (lane & 3) * 2;
    #pragma unroll
    for (int mt = 0; mt < 2; mt++) {
        #pragma unroll
        for (int half = 0; half < 2; half++) {
            int m_g = m0 + wm * 32 + mt * 16 + qrow + half * 8;
            if (m_g < n) {
                TOUT* crow = C + (size_t)m_g * CST;
                #pragma unroll
                for (int j = 0; j < NT; j++) {
                    int n_g = wn * WN + j * 8 + qcol;
                    if (CST == 128 || n_g < CST) {
                        float v0 = c[mt][j][half * 2];
                        float v1 = c[mt][j][half * 2 + 1];
                        if constexpr (sizeof(TOUT) == 2) {
                            __half2 hv = __floats2half2_rn(v0, v1);
                            *reinterpret_cast<__half2*>(crow + n_g) = hv;
                        } else {
                            *reinterpret_cast<float2*>(crow + n_g) =
                                make_float2(v0, v1);
                        }
                    }
                }
            }
        }
    }
}

// ---------------- MMA compute core (8 warps, tile 128 x NOUT) ----------------
template<int NOUT, int NT>
__device__ __forceinline__ void mma_tile(
    uint32_t aB, uint32_t wB, float c[2][NT][4],
    uint32_t aRow0, uint32_t aRow1, const uint32_t* bRowByte)
{
    #pragma unroll
    for (int ks = 0; ks < 8; ks++) {
        const uint32_t kb = ks * 32;
        uint32_t a[2][4];
        ldsm4(aB + aRow0 + kb, a[0][0], a[0][1], a[0][2], a[0][3]);
        ldsm4(aB + aRow1 + kb, a[1][0], a[1][1], a[1][2], a[1][3]);
        uint32_t b[NT][2];
        #pragma unroll
        for (int jp = 0; jp < NT / 2; jp++)
            ldsm4(wB + bRowByte[jp] + kb,
                  b[2 * jp][0], b[2 * jp][1], b[2 * jp + 1][0], b[2 * jp + 1][1]);
        #pragma unroll
        for (int mt = 0; mt < 2; mt++)
            #pragma unroll
            for (int j = 0; j < NT; j++)
                mma_f16(c[mt][j], a[mt], b[j][0], b[j][1]);
    }
}

// ================================================================
// kernel 1: Y(fp16) = fp16(X) @ fp16(W1)^T — tile 128x128, 2 CTAs/SM.
// smem: [A 128*RS][W 128*RS]
// ================================================================
__global__ __launch_bounds__(256, 2) void gemm_first_kernel(
    const float* __restrict__ X, const float* __restrict__ W,
    __half* __restrict__ C, int n)
{
    extern __shared__ char smem[];
    constexpr int OFF_W = 128 * RS;
    const int tid  = threadIdx.x;
    const int wid  = tid >> 5;
    const int lane = tid & 31;
    const int wm   = wid >> 1;
    const int wn   = wid & 1;
    const int m0   = blockIdx.x * 128;

    #pragma unroll
    for (int i = 0; i < 16; i++) {
        int t = i * 256 + tid;              // 4096 float4
        int row = t >> 5;
        int c4  = t & 31;
        int grow = m0 + row;
        float4 v = make_float4(0.f, 0.f, 0.f, 0.f);
        if (grow < n)
            v = __ldg(reinterpret_cast<const float4*>(X + (size_t)grow * 128) + c4);
        __half h[4] = { __float2half(v.x), __float2half(v.y),
                        __float2half(v.z), __float2half(v.w) };
        *reinterpret_cast<uint2*>(smem + row * RS + c4 * 8) =
            *reinterpret_cast<uint2*>(h);
    }
    load_w_cvt<128, 0>(smem, OFF_W, W);
    __syncthreads();

    const uint32_t sb = smem_u32(smem);
    const int l15   = lane & 15;
    const int aHalf = (lane & 16) ? 16 : 0;
    const uint32_t aRow0 = (uint32_t)((wm * 32 + l15) * RS + aHalf);
    const uint32_t aRow1 = aRow0 + 16 * RS;
    const int bRow  = (lane & 7) + ((lane & 16) ? 8 : 0);
    const int bHalf = (lane & 8) ? 16 : 0;
    uint32_t bRowByte[4];
    #pragma unroll
    for (int jp = 0; jp < 4; jp++)
        bRowByte[jp] = (uint32_t)((wn * 64 + jp * 16 + bRow) * RS + bHalf);

    float c[2][8][4];
    #pragma unroll
    for (int mt = 0; mt < 2; mt++)
        #pragma unroll
        for (int j = 0; j < 8; j++)
            #pragma unroll
            for (int q = 0; q < 4; q++) c[mt][j][q] = 0.f;

    mma_tile<128, 8>(sb, sb + OFF_W, c, aRow0, aRow1, bRowByte);
    epilogue_store<64, 8, 128>(c, C, m0, n, wm, wn, lane);
}

// ================================================================
// kernels 3/5: persistent GEMM, tile 128 x NOUT, 256 thr, 2 CTAs/SM.
// smem: [W NOUT*RS][Abuf0 128*RS][Abuf1 128*RS]
// ================================================================
template<int NOUT, int CST, int PADC, typename TOUT>
__global__ __launch_bounds__(256, 2) void gemm_pers_kernel(
    const __half* __restrict__ A, const float* __restrict__ W,
    TOUT* __restrict__ C, int n)
{
    extern __shared__ char smem[];
    constexpr int OFF_A0 = NOUT * RS;
    constexpr int ABUF   = 128 * RS;
    constexpr int WN = NOUT / 2;
    constexpr int NT = WN / 8;

    const int tid  = threadIdx.x;
    const int wid  = tid >> 5;
    const int lane = tid & 31;
    const int wm   = wid >> 1;         // 0..3
    const int wn   = wid & 1;          // 0..1
    const uint32_t sb = smem_u32(smem);

    load_w_cvt<NOUT, PADC>(smem, 0, W);

    const int tiles  = (n + 127) >> 7;
    const int stride = gridDim.x;

    auto prefetch = [&](int t, int buf) {
        const uint32_t abase = sb + OFF_A0 + buf * ABUF;
        const int m0 = t << 7;
        #pragma unroll
        for (int i = 0; i < 8; i++) {
            int k = i * 256 + tid;         // 2048: row 0..127, c16 0..15
            int row = k >> 4;
            int c16 = k & 15;
            int grow = m0 + row;
            uint32_t sz = (grow < n) ? 16u : 0u;
            int gc = (grow < n) ? grow : 0;
            size_t g = (size_t)gc * 128 + c16 * 8;
            cp_async16(abase + (uint32_t)(row * RS + c16 * 16), A + g, sz);
        }
    };

    const int l15   = lane & 15;
    const int aHalf = (lane & 16) ? 16 : 0;
    const uint32_t aRowOff0 = (uint32_t)((wm * 32 + l15) * RS + aHalf);
    const uint32_t aRowOff1 = aRowOff0 + 16 * RS;
    const int bRow  = (lane & 7) + ((lane & 16) ? 8 : 0);
    const int bHalf = (lane & 8) ? 16 : 0;
    uint32_t bRowByte[NT / 2];
    #pragma unroll
    for (int jp = 0; jp < NT / 2; jp++)
        bRowByte[jp] = (uint32_t)((wn * WN + jp * 16 + bRow) * RS + bHalf);

    int t0 = blockIdx.x;
    if (t0 < tiles) prefetch(t0, 0);
    CP_COMMIT();

    int it = 0;
    for (int t = t0; t < tiles; t += stride, it++) {
        const int buf = it & 1;
        int tn = t + stride;
        if (tn < tiles) prefetch(tn, buf ^ 1);
        CP_COMMIT();
        CP_WAIT1();
        __syncthreads();

        const uint32_t aB = sb + OFF_A0 + buf * ABUF;

        float c[2][NT][4];
        #pragma unroll
        for (int mt = 0; mt < 2; mt++)
            #pragma unroll
            for (int j = 0; j < NT; j++)
                #pragma unroll
                for (int q = 0; q < 4; q++) c[mt][j][q] = 0.f;

        mma_tile<NOUT, NT>(aB, sb, c, aRowOff0, aRowOff1, bRowByte);
        epilogue_store<WN, NT, CST>(c, C, t << 7, n, wm, wn, lane);
        __syncthreads();   // buf fully consumed before refill
    }
}

// ---------------- gather: HADD2 pairs -> fp32 accumulation -------------------
__global__ __launch_bounds__(256) void gather_h16_kernel(
    const __half* __restrict__ Y, const int* __restrict__ nbrs,
    __half* __restrict__ H, int n)
{
    const int warp = (blockIdx.x * blockDim.x + threadIdx.x) >> 5;
    const int lane = threadIdx.x & 31;
    if (warp >= n) return;

    int idx = 0;
    if (lane < SAMPLE) idx = nbrs[(size_t)warp * SAMPLE + lane];

    float a0 = 0.f, a1 = 0.f, a2 = 0.f, a3 = 0.f;
    #pragma unroll
    for (int jp = 0; jp < SAMPLE / 2; jp++) {
        int r0 = __shfl_sync(0xffffffffu, idx, 2 * jp);
        int r1 = __shfl_sync(0xffffffffu, idx, 2 * jp + 1);
        uint2 u0 = __ldg(reinterpret_cast<const uint2*>(Y + (size_t)r0 * 128) + lane);
        uint2 u1 = __ldg(reinterpret_cast<const uint2*>(Y + (size_t)r1 * 128) + lane);
        __half2 s0 = __hadd2(*reinterpret_cast<__half2*>(&u0.x),
                             *reinterpret_cast<__half2*>(&u1.x));
        __half2 s1 = __hadd2(*reinterpret_cast<__half2*>(&u0.y),
                             *reinterpret_cast<__half2*>(&u1.y));
        float2 f0 = __half22float2(s0);
        float2 f1 = __half22float2(s1);
        a0 += f0.x; a1 += f0.y; a2 += f1.x; a3 += f1.y;
    }
    {
        int r = __shfl_sync(0xffffffffu, idx, SAMPLE - 1);
        uint2 u = __ldg(reinterpret_cast<const uint2*>(Y + (size_t)r * 128) + lane);
        float2 f0 = __half22float2(*reinterpret_cast<__half2*>(&u.x));
        float2 f1 = __half22float2(*reinterpret_cast<__half2*>(&u.y));
        a0 += f0.x; a1 += f0.y; a2 += f1.x; a3 += f1.y;
    }
    const float s = 1.0f / (float)SAMPLE;
    __half h[4] = { __float2half(fmaxf(a0 * s, 0.f)),
                    __float2half(fmaxf(a1 * s, 0.f)),
                    __float2half(fmaxf(a2 * s, 0.f)),
                    __float2half(fmaxf(a3 * s, 0.f)) };
    *(reinterpret_cast<uint2*>(H + (size_t)warp * 128) + lane) =
        *reinterpret_cast<uint2*>(h);
}

// ================================================================
extern "C" void kernel_launch(void* const* d_in, const int* in_sizes, int n_in,
                              void* d_out, int out_size)
{
    const float* X    = (const float*)d_in[0];
    const int*   nbrs = (const int*)  d_in[1];
    const float* W1   = (const float*)d_in[2];
    const float* W2   = (const float*)d_in[3];
    const float* WL   = (const float*)d_in[4];
    float*       out  = (float*)d_out;
    const int n = in_sizes[1] / SAMPLE;

    __half *Y, *H;
    cudaGetSymbolAddress((void**)&Y, g_Y);
    cudaGetSymbolAddress((void**)&H, g_H);

    const int SMF    = RS * (128 + 128);          //  69632
    const int SMP128 = RS * 128 + 2 * RS * 128;   // 104448
    const int SMP64  = RS * 64  + 2 * RS * 128;   //  87040
    cudaFuncSetAttribute(gemm_first_kernel,
                         cudaFuncAttributeMaxDynamicSharedMemorySize, SMF);
    cudaFuncSetAttribute(gemm_pers_kernel<128, 128, 0, __half>,
                         cudaFuncAttributeMaxDynamicSharedMemorySize, SMP128);
    cudaFuncSetAttribute(gemm_pers_kernel<64, 40, CLASSES, float>,
                         cudaFuncAttributeMaxDynamicSharedMemorySize, SMP64);

    const int gg = (n + 127) / 128;
    const int ag = (n + 7) / 8;

    gemm_first_kernel<<<gg, 256, SMF>>>(X, W1, Y, n);
    gather_h16_kernel<<<ag, 256>>>(Y, nbrs, H, n);
    gemm_pers_kernel<128, 128, 0, __half><<<NPERS, 256, SMP128>>>(H, W2, Y, n);
    gather_h16_kernel<<<ag, 256>>>(Y, nbrs, H, n);
    gemm_pers_kernel<64, 40, CLASSES, float><<<NPERS, 256, SMP64>>>(H, WL, out, n);
}